// round 13
// baseline (speedup 1.0000x reference)
#include <cuda_runtime.h>
#include <cstdint>

// Problem constants
#define TT 16384
#define HH 100
#define HE 104          // extended h: [h(100), x0, x1, x2, 1]
#define NT 400          // one thread per gate-row

// Hidden states [t][u]
__device__ float g_hs[TT * HH];

// ---------------------------------------------------------------------------
__device__ __forceinline__ float2 ffma2(float2 a, float2 b, float2 c) {
    float2 r;
    asm("fma.rn.f32x2 %0, %1, %2, %3;"
        : "=l"(reinterpret_cast<unsigned long long&>(r))
        : "l"(reinterpret_cast<unsigned long long&>(a)),
          "l"(reinterpret_cast<unsigned long long&>(b)),
          "l"(reinterpret_cast<unsigned long long&>(c)));
    return r;
}
__device__ __forceinline__ float2 fadd2(float2 a, float2 b) {
    float2 r;
    asm("add.rn.f32x2 %0, %1, %2;"
        : "=l"(reinterpret_cast<unsigned long long&>(r))
        : "l"(reinterpret_cast<unsigned long long&>(a)),
          "l"(reinterpret_cast<unsigned long long&>(b)));
    return r;
}
__device__ __forceinline__ float tanh_approx(float x) {
    float r; asm("tanh.approx.f32 %0, %1;" : "=f"(r) : "f"(x)); return r;
}
__device__ __forceinline__ float ex2_approx(float x) {
    float r; asm("ex2.approx.f32 %0, %1;" : "=f"(r) : "f"(x)); return r;
}
__device__ __forceinline__ float rcp_approx(float x) {
    float r; asm("rcp.approx.f32 %0, %1;" : "=f"(r) : "f"(x)); return r;
}

#define LOG2E 1.4426950408889634f

// ---------------------------------------------------------------------------
// Fused LSTM + projection. ONE block, 400 threads (12.5 warps).
// Thread = one gate-row: q = tid&3 (gate i,f,g,o), u = tid>>2 (unit 0..99).
// Each thread holds ONE extended 104-wide row [Whh | Wih | bias] in regs
// (52 float2 = 104 regs; cap at 400 thr is 163 -> no spill) and computes the
// FULL preactivation as one dot with h~ = [h, x_t, 1].
// Per step/thread: 26 broadcast LDS.128 + 52 FFMA2 (4 chains) + 1 MUFU.TANH
// + 3 quad shfls + replicated c/h. Worst SMSP: 3.25 warps x 52 warp-FFMA2
// -> ~338 cyc FMA phase (vs 400 in R9's 2-warp-SMSP layout).
// One __syncthreads per step (double-buffered extended h).
// ---------------------------------------------------------------------------
__global__ void __launch_bounds__(NT, 1)
k_lstm_fused(const float* __restrict__ x,
             const float* __restrict__ Whh,
             const float* __restrict__ Wih,
             const float* __restrict__ bih,
             const float* __restrict__ bhh,
             const float* __restrict__ Wlin,
             const float* __restrict__ blin,
             float* __restrict__ out) {
    extern __shared__ __align__(16) float sx[];        // [TT*3] input table
    __shared__ __align__(16) float sh[2][HE];          // extended h, 2 buffers
    __shared__ float sWl[HH];
    __shared__ float sbl;

    const int tid = threadIdx.x;         // 0..399
    const int q   = tid & 3;             // gate (i,f,g,o)
    const int u   = tid >> 2;            // unit 0..99
    const int l   = tid & 31;
    const int qb  = l & ~3;              // quad base lane
    // Warp 12 holds threads 384..399 (lanes 0..15)
    const unsigned mask = (tid >= 384) ? 0x0000FFFFu : 0xFFFFFFFFu;

    const int row = q * HH + u;

    // act = A0*tanh(S0*g)+B0 : q==2 -> tanh(1,1,0), else sigmoid(.5,.5,.5)
    const float S0 = (q == 2) ? 1.0f : 0.5f;
    const float A0 = (q == 2) ? 1.0f : 0.5f;
    const float B0 = (q == 2) ? 0.0f : 0.5f;

    // Extended weight row: [Whh(100) | Wih(3) | bias]  (52 float2)
    float2 w[52];
    {
        const float bias = bih[row] + bhh[row];
        #pragma unroll
        for (int j = 0; j < 52; j++) {
            int k0 = 2 * j, k1 = 2 * j + 1;
            float v0 = (k0 < HH) ? Whh[row * HH + k0]
                     : (k0 < 103) ? Wih[row * 3 + (k0 - HH)] : bias;
            float v1 = (k1 < HH) ? Whh[row * HH + k1]
                     : (k1 < 103) ? Wih[row * 3 + (k1 - HH)] : bias;
            w[j] = make_float2(v0, v1);
        }
    }

    // Preload x table (coalesced); stage W_lin; init h buffers
    {
        const float4* xs = reinterpret_cast<const float4*>(x);
        float4* xd = reinterpret_cast<float4*>(sx);
        for (int i = tid; i < TT * 3 / 4; i += NT) xd[i] = xs[i];
    }
    if (tid < HH) sWl[tid] = Wlin[tid];
    if (tid == 0) sbl = blin[0];
    if (tid < HH) { sh[0][tid] = 0.0f; sh[1][tid] = 0.0f; }
    if (tid == 0) { sh[0][103] = 1.0f; sh[1][103] = 1.0f; }
    __syncthreads();
    if (tid < 3) sh[0][100 + tid] = sx[tid];       // x(0) into buffer 0
    __syncthreads();

    float c = 0.0f;

    #pragma unroll 1
    for (int t = 0; t < TT; t++) {
        const int rb = t & 1;
        const float4* hp = reinterpret_cast<const float4*>(&sh[rb][0]);

        // 104-wide dot (full preactivation): 26 LDS.128 + 52 FFMA2, 4 chains
        float2 c00 = make_float2(0.0f, 0.0f), c01 = make_float2(0.0f, 0.0f);
        float2 c10 = make_float2(0.0f, 0.0f), c11 = make_float2(0.0f, 0.0f);
        #pragma unroll
        for (int i = 0; i < 13; i++) {
            float4 hv = hp[i];
            c00 = ffma2(make_float2(hv.x, hv.y), w[2 * i],     c00);
            c01 = ffma2(make_float2(hv.z, hv.w), w[2 * i + 1], c01);
        }
        #pragma unroll
        for (int i = 13; i < 26; i++) {
            float4 hv = hp[i];
            c10 = ffma2(make_float2(hv.x, hv.y), w[2 * i],     c10);
            c11 = ffma2(make_float2(hv.z, hv.w), w[2 * i + 1], c11);
        }
        float2 s = fadd2(fadd2(c00, c10), fadd2(c01, c11));
        float gt = s.x + s.y;

        // This lane's gate activation (single MUFU.TANH)
        float a = fmaf(A0, tanh_approx(S0 * gt), B0);

        // Gather the quad's four activations
        float ai = __shfl_sync(mask, a, qb + 0);
        float af = __shfl_sync(mask, a, qb + 1);
        float ag = __shfl_sync(mask, a, qb + 2);
        float ao = __shfl_sync(mask, a, qb + 3);

        // Replicated c/h update (identical across the quad)
        c = fmaf(af, c, ai * ag);
        float hn = ao * tanh_approx(c);

        if (q == 0) {
            sh[rb ^ 1][u]    = hn;
            g_hs[t * HH + u] = hn;
        } else if (q == 1 && u < 3) {
            // stage x(t+1) into the write buffer
            int tn = (t + 1 < TT) ? (t + 1) : t;
            sh[rb ^ 1][100 + u] = sx[3 * tn + u];
        }
        __syncthreads();
    }

    // ---- projection tail: out[t] = sigmoid(sum_u hs[t][u]*Wl[u] + b) ----
    const float bl = sbl;
    for (int t = tid; t < TT; t += NT) {
        const float4* hr = reinterpret_cast<const float4*>(g_hs + t * HH);
        float s0 = 0.0f, s1 = 0.0f;
        #pragma unroll
        for (int j = 0; j < 25; j++) {
            float4 hv = hr[j];
            const float* wl = sWl + 4 * j;
            s0 = fmaf(hv.x, wl[0], s0);
            s1 = fmaf(hv.y, wl[1], s1);
            s0 = fmaf(hv.z, wl[2], s0);
            s1 = fmaf(hv.w, wl[3], s1);
        }
        float z = s0 + s1 + bl;
        out[t] = rcp_approx(1.0f + ex2_approx(-LOG2E * z));
    }
}

// ---------------------------------------------------------------------------
// Launch.  Inputs: input_x, W_ih, W_hh, b_ih, b_hh, W_lin, b_lin
// ---------------------------------------------------------------------------
extern "C" void kernel_launch(void* const* d_in, const int* in_sizes, int n_in,
                              void* d_out, int out_size) {
    const float* x    = (const float*)d_in[0];
    const float* Wih  = (const float*)d_in[1];
    const float* Whh  = (const float*)d_in[2];
    const float* bih  = (const float*)d_in[3];
    const float* bhh  = (const float*)d_in[4];
    const float* Wlin = (const float*)d_in[5];
    const float* blin = (const float*)d_in[6];
    float* out = (float*)d_out;

    (void)in_sizes; (void)n_in; (void)out_size;

    const int smem_bytes = TT * 3 * (int)sizeof(float);   // 192 KB (x table)
    static bool attr_set = false;
    if (!attr_set) {
        cudaFuncSetAttribute(k_lstm_fused,
                             cudaFuncAttributeMaxDynamicSharedMemorySize,
                             smem_bytes);
        attr_set = true;
    }

    k_lstm_fused<<<1, NT, smem_bytes>>>(x, Whh, Wih, bih, bhh,
                                        Wlin, blin, out);
}

// round 15
// speedup vs baseline: 1.6227x; 1.6227x over previous
#include <cuda_runtime.h>
#include <cstdint>

// Problem constants
#define TT 16384
#define HH 100
#define HE 104          // extended h: [h(100), x0, x1, x2, 1]
#define KS 52           // k-slice per thread (half of HE)
#define NT 200          // threads: 2 per unit (k-halves)

// Hidden states [t][u]
__device__ float g_hs[TT * HH];

// ---------------------------------------------------------------------------
__device__ __forceinline__ float2 ffma2(float2 a, float2 b, float2 c) {
    float2 r;
    asm("fma.rn.f32x2 %0, %1, %2, %3;"
        : "=l"(reinterpret_cast<unsigned long long&>(r))
        : "l"(reinterpret_cast<unsigned long long&>(a)),
          "l"(reinterpret_cast<unsigned long long&>(b)),
          "l"(reinterpret_cast<unsigned long long&>(c)));
    return r;
}
__device__ __forceinline__ float2 fadd2(float2 a, float2 b) {
    float2 r;
    asm("add.rn.f32x2 %0, %1, %2;"
        : "=l"(reinterpret_cast<unsigned long long&>(r))
        : "l"(reinterpret_cast<unsigned long long&>(a)),
          "l"(reinterpret_cast<unsigned long long&>(b)));
    return r;
}
__device__ __forceinline__ float tanh_approx(float x) {
    float r; asm("tanh.approx.f32 %0, %1;" : "=f"(r) : "f"(x)); return r;
}
__device__ __forceinline__ float ex2_approx(float x) {
    float r; asm("ex2.approx.f32 %0, %1;" : "=f"(r) : "f"(x)); return r;
}
__device__ __forceinline__ float rcp_approx(float x) {
    float r; asm("rcp.approx.f32 %0, %1;" : "=f"(r) : "f"(x)); return r;
}

#define LOG2E 1.4426950408889634f

// sigmoid via single MUFU.TANH
__device__ __forceinline__ float sigmoid_t(float x) {
    return fmaf(0.5f, tanh_approx(0.5f * x), 0.5f);
}

// ---------------------------------------------------------------------------
// Fused LSTM + projection. ONE block, 200 threads (6.25 warps).
// Thread (u = tid>>1, kh = tid&1) holds ALL FOUR extended gate rows of unit
// u over the k-slice [52*kh, 52*kh+52): 4 x 26 float2 = 208 weight regs.
// Per step/thread: 13 broadcast LDS.128 shared across the 4 rows (cuts the
// SM-wide warp-LDS.128 count from R9's 156 to 81 -- the crossbar-delivery
// bottleneck identified from R1/R5/R9/R13 timings), 104 FFMA2 (8 chains,
// depth 13), FOUR shfl_xor(1) k-half merges, all four activations computed
// locally (no gate gathering), replicated c/h, one barrier.
// Extended h~ = [h, x_t, 1] folds the x contribution and bias into the dot.
// ---------------------------------------------------------------------------
__global__ void __launch_bounds__(NT, 1)
k_lstm_fused(const float* __restrict__ x,
             const float* __restrict__ Whh,
             const float* __restrict__ Wih,
             const float* __restrict__ bih,
             const float* __restrict__ bhh,
             const float* __restrict__ Wlin,
             const float* __restrict__ blin,
             float* __restrict__ out) {
    extern __shared__ __align__(16) float sx[];        // [TT*3] input table
    __shared__ __align__(16) float sh[2][HE];          // extended h, 2 buffers
    __shared__ float sWl[HH];
    __shared__ float sbl;

    const int tid = threadIdx.x;         // 0..199
    const int kh  = tid & 1;             // k-half
    const int u   = tid >> 1;            // unit 0..99
    // Warp 6 holds threads 192..199 (lanes 0..7)
    const unsigned mask = (tid >= 192) ? 0x000000FFu : 0xFFFFFFFFu;

    // Four extended gate-row slices: w[g][j] covers k = 52*kh + 2j, +1
    float2 w[4][26];
    #pragma unroll
    for (int g = 0; g < 4; g++) {
        const int row = g * HH + u;
        const float bias = bih[row] + bhh[row];
        #pragma unroll
        for (int j = 0; j < 26; j++) {
            int k0 = KS * kh + 2 * j;
            int k1 = k0 + 1;
            float v0 = (k0 < HH) ? Whh[row * HH + k0]
                     : (k0 < 103) ? Wih[row * 3 + (k0 - HH)] : bias;
            float v1 = (k1 < HH) ? Whh[row * HH + k1]
                     : (k1 < 103) ? Wih[row * 3 + (k1 - HH)] : bias;
            w[g][j] = make_float2(v0, v1);
        }
    }

    // Preload x table (coalesced); stage W_lin; init h buffers
    {
        const float4* xs = reinterpret_cast<const float4*>(x);
        float4* xd = reinterpret_cast<float4*>(sx);
        for (int i = tid; i < TT * 3 / 4; i += NT) xd[i] = xs[i];
    }
    if (tid < HH) sWl[tid] = Wlin[tid];
    if (tid == 0) sbl = blin[0];
    if (tid < HH) { sh[0][tid] = 0.0f; sh[1][tid] = 0.0f; }
    if (tid == 0) { sh[0][103] = 1.0f; sh[1][103] = 1.0f; }
    __syncthreads();
    if (tid < 3) sh[0][100 + tid] = sx[tid];       // x(0) into buffer 0
    __syncthreads();

    float c = 0.0f;

    #pragma unroll 1
    for (int t = 0; t < TT; t++) {
        const int rb = t & 1;
        // This thread's 13-float4 window of the extended h buffer
        const float4* hp = reinterpret_cast<const float4*>(&sh[rb][0])
                         + kh * (KS / 4);

        // 4 row-slices x 52-wide: 13 LDS.128 + 104 FFMA2 (8 chains, depth 13)
        float2 a0l = make_float2(0.f, 0.f), a0h = make_float2(0.f, 0.f);
        float2 a1l = make_float2(0.f, 0.f), a1h = make_float2(0.f, 0.f);
        float2 a2l = make_float2(0.f, 0.f), a2h = make_float2(0.f, 0.f);
        float2 a3l = make_float2(0.f, 0.f), a3h = make_float2(0.f, 0.f);
        #pragma unroll
        for (int j = 0; j < 13; j++) {
            float4 hv = hp[j];
            float2 lo = make_float2(hv.x, hv.y);
            float2 hi = make_float2(hv.z, hv.w);
            a0l = ffma2(lo, w[0][2 * j],     a0l);
            a0h = ffma2(hi, w[0][2 * j + 1], a0h);
            a1l = ffma2(lo, w[1][2 * j],     a1l);
            a1h = ffma2(hi, w[1][2 * j + 1], a1h);
            a2l = ffma2(lo, w[2][2 * j],     a2l);
            a2h = ffma2(hi, w[2][2 * j + 1], a2h);
            a3l = ffma2(lo, w[3][2 * j],     a3l);
            a3h = ffma2(hi, w[3][2 * j + 1], a3h);
        }
        float2 t0 = fadd2(a0l, a0h);
        float2 t1 = fadd2(a1l, a1h);
        float2 t2 = fadd2(a2l, a2h);
        float2 t3 = fadd2(a3l, a3h);
        float s0 = t0.x + t0.y;
        float s1 = t1.x + t1.y;
        float s2 = t2.x + t2.y;
        float s3 = t3.x + t3.y;

        // Merge k-halves (partner = lane^1)
        float g0 = s0 + __shfl_xor_sync(mask, s0, 1);
        float g1 = s1 + __shfl_xor_sync(mask, s1, 1);
        float g2 = s2 + __shfl_xor_sync(mask, s2, 1);
        float g3 = s3 + __shfl_xor_sync(mask, s3, 1);

        // All four activations locally (4 MUFU.TANH)
        float ai = sigmoid_t(g0);
        float af = sigmoid_t(g1);
        float ag = tanh_approx(g2);
        float ao = sigmoid_t(g3);

        // c/h update (replicated on the 2 k-half threads)
        c = fmaf(af, c, ai * ag);
        float hn = ao * tanh_approx(c);

        if (kh == 0) {
            sh[rb ^ 1][u]    = hn;
            g_hs[t * HH + u] = hn;
        } else if (u < 3) {
            // kh==1, u<3 (tid 1,3,5): stage x(t+1) into the write buffer
            int tn = (t + 1 < TT) ? (t + 1) : t;
            sh[rb ^ 1][100 + u] = sx[3 * tn + u];
        }
        __syncthreads();
    }

    // ---- projection tail: out[t] = sigmoid(sum_u hs[t][u]*Wl[u] + b) ----
    const float bl = sbl;
    for (int t = tid; t < TT; t += NT) {
        const float4* hr = reinterpret_cast<const float4*>(g_hs + t * HH);
        float s0 = 0.0f, s1 = 0.0f;
        #pragma unroll
        for (int j = 0; j < 25; j++) {
            float4 hv = hr[j];
            const float* wl = sWl + 4 * j;
            s0 = fmaf(hv.x, wl[0], s0);
            s1 = fmaf(hv.y, wl[1], s1);
            s0 = fmaf(hv.z, wl[2], s0);
            s1 = fmaf(hv.w, wl[3], s1);
        }
        float z = s0 + s1 + bl;
        out[t] = rcp_approx(1.0f + ex2_approx(-LOG2E * z));
    }
}

// ---------------------------------------------------------------------------
// Launch.  Inputs: input_x, W_ih, W_hh, b_ih, b_hh, W_lin, b_lin
// ---------------------------------------------------------------------------
extern "C" void kernel_launch(void* const* d_in, const int* in_sizes, int n_in,
                              void* d_out, int out_size) {
    const float* x    = (const float*)d_in[0];
    const float* Wih  = (const float*)d_in[1];
    const float* Whh  = (const float*)d_in[2];
    const float* bih  = (const float*)d_in[3];
    const float* bhh  = (const float*)d_in[4];
    const float* Wlin = (const float*)d_in[5];
    const float* blin = (const float*)d_in[6];
    float* out = (float*)d_out;

    (void)in_sizes; (void)n_in; (void)out_size;

    const int smem_bytes = TT * 3 * (int)sizeof(float);   // 192 KB (x table)
    static bool attr_set = false;
    if (!attr_set) {
        cudaFuncSetAttribute(k_lstm_fused,
                             cudaFuncAttributeMaxDynamicSharedMemorySize,
                             smem_bytes);
        attr_set = true;
    }

    k_lstm_fused<<<1, NT, smem_bytes>>>(x, Whh, Wih, bih, bhh,
                                        Wlin, blin, out);
}

// round 17
// speedup vs baseline: 1.9642x; 1.2105x over previous
#include <cuda_runtime.h>
#include <cstdint>

// Problem constants
#define TT 16384
#define HH 100

// Hidden states [t][u]
__device__ float g_hs[TT * HH];

// ---------------------------------------------------------------------------
__device__ __forceinline__ float2 ffma2(float2 a, float2 b, float2 c) {
    float2 r;
    asm("fma.rn.f32x2 %0, %1, %2, %3;"
        : "=l"(reinterpret_cast<unsigned long long&>(r))
        : "l"(reinterpret_cast<unsigned long long&>(a)),
          "l"(reinterpret_cast<unsigned long long&>(b)),
          "l"(reinterpret_cast<unsigned long long&>(c)));
    return r;
}
__device__ __forceinline__ float2 fadd2(float2 a, float2 b) {
    float2 r;
    asm("add.rn.f32x2 %0, %1, %2;"
        : "=l"(reinterpret_cast<unsigned long long&>(r))
        : "l"(reinterpret_cast<unsigned long long&>(a)),
          "l"(reinterpret_cast<unsigned long long&>(b)));
    return r;
}
__device__ __forceinline__ float tanh_approx(float x) {
    float r; asm("tanh.approx.f32 %0, %1;" : "=f"(r) : "f"(x)); return r;
}
__device__ __forceinline__ float ex2_approx(float x) {
    float r; asm("ex2.approx.f32 %0, %1;" : "=f"(r) : "f"(x)); return r;
}
__device__ __forceinline__ float rcp_approx(float x) {
    float r; asm("rcp.approx.f32 %0, %1;" : "=f"(r) : "f"(x)); return r;
}

#define LOG2E 1.4426950408889634f

// ---------------------------------------------------------------------------
// Sequential LSTM. ONE block, 200 threads (6.25 warps).
// Thread pair (2u, 2u+1) handles unit u:
//   even thread: gate rows i (u), f (100+u)          -> both sigmoid
//   odd  thread: gate rows g (200+u), o (300+u)      -> tanh, sigmoid
// 200 weight floats in registers (255-reg cap at 200 threads -> no spill).
// PRESCALED weights: sigmoid rows are scaled by 0.5 at load (incl. Wih and
// bias), so sigmoid(z) = 0.5*tanh(z') + 0.5 needs no FMUL before the
// MUFU.TANH -- shortens the serial activation chain that follows the
// FMA-pipe-bound dot phase.
// Per step: 25 broadcast LDS.128 + 100 FFMA2 (4 indep chains), 1 MUFU.TANH
// per slot, ONE shfl_xor pair-exchange (x2 values), replicated c/h tail,
// one barrier. Loop unrolled x2 (no buffer selects).
// ---------------------------------------------------------------------------
__global__ void __launch_bounds__(200, 1)
k_lstm_seq(const float* __restrict__ x,
           const float* __restrict__ Whh,
           const float* __restrict__ Wih,
           const float* __restrict__ bih,
           const float* __restrict__ bhh) {
    extern __shared__ __align__(16) float sx[];        // [TT*3] input (192 KB)
    __shared__ __align__(16) float sh[2][HH];          // h double buffer

    const int tid = threadIdx.x;          // 0..199
    const int odd = tid & 1;
    const int u   = tid >> 1;             // 0..99
    // Warp 6 holds only threads 192..199 (lanes 0..7)
    const unsigned mask = (tid >= 192) ? 0x000000FFu : 0xFFFFFFFFu;

    const int r0 = odd * 2 * HH + u;      // even: i-row, odd: g-row
    const int r1 = r0 + HH;               // even: f-row, odd: o-row

    // slot0: even -> sigmoid (prescale 0.5, A=.5 B=.5); odd -> tanh (1,1,0)
    const float P0 = odd ? 1.0f : 0.5f;
    const float A0 = odd ? 1.0f : 0.5f;
    const float B0 = odd ? 0.0f : 0.5f;
    // slot1 is always sigmoid: prescale 0.5

    // Both weight rows -> registers (2 x 50 float2 = 200 regs), prescaled
    float2 w0[50], w1[50];
    {
        const float2* p0 = reinterpret_cast<const float2*>(Whh + r0 * HH);
        const float2* p1 = reinterpret_cast<const float2*>(Whh + r1 * HH);
        #pragma unroll
        for (int i = 0; i < 50; i++) {
            float2 a = p0[i]; a.x *= P0;   a.y *= P0;   w0[i] = a;
            float2 b = p1[i]; b.x *= 0.5f; b.y *= 0.5f; w1[i] = b;
        }
    }
    const float wa0 = P0 * Wih[r0 * 3],  wa1 = P0 * Wih[r0 * 3 + 1],
                wa2 = P0 * Wih[r0 * 3 + 2];
    const float wb0 = 0.5f * Wih[r1 * 3], wb1 = 0.5f * Wih[r1 * 3 + 1],
                wb2 = 0.5f * Wih[r1 * 3 + 2];
    const float bias0 = P0 * (bih[r0] + bhh[r0]);
    const float bias1 = 0.5f * (bih[r1] + bhh[r1]);

    // Preload x into SMEM (coalesced float4); zero h buffers
    {
        const float4* xs = reinterpret_cast<const float4*>(x);
        float4* xd = reinterpret_cast<float4*>(sx);
        for (int i = tid; i < TT * 3 / 4; i += 200) xd[i] = xs[i];
    }
    if (tid < 2 * HH) (&sh[0][0])[tid] = 0.0f;
    __syncthreads();

    float c = 0.0f;
    const float* xr = sx;
    const float4* hp0 = reinterpret_cast<const float4*>(&sh[0][0]);
    const float4* hp1 = reinterpret_cast<const float4*>(&sh[1][0]);

// S = sub-step (0/1); actual timestep is t + S (FIXED vs R16: g_hs index)
#define BODY(S, RP, WROW)                                                     \
    {                                                                         \
        const float xv0 = xr[3*(S)+0], xv1 = xr[3*(S)+1], xv2 = xr[3*(S)+2];  \
        float xg0 = fmaf(wa2, xv2, fmaf(wa1, xv1, fmaf(wa0, xv0, bias0)));    \
        float xg1 = fmaf(wb2, xv2, fmaf(wb1, xv1, fmaf(wb0, xv0, bias1)));    \
        float2 a00 = make_float2(xg0, 0.0f), a01 = make_float2(0.0f, 0.0f);   \
        float2 a10 = make_float2(xg1, 0.0f), a11 = make_float2(0.0f, 0.0f);   \
        _Pragma("unroll")                                                     \
        for (int i = 0; i < 25; i++) {                                        \
            float4 hv = (RP)[i];                                              \
            float2 lo = make_float2(hv.x, hv.y);                              \
            float2 hi = make_float2(hv.z, hv.w);                              \
            a00 = ffma2(lo, w0[2 * i],     a00);                              \
            a01 = ffma2(hi, w0[2 * i + 1], a01);                              \
            a10 = ffma2(lo, w1[2 * i],     a10);                              \
            a11 = ffma2(hi, w1[2 * i + 1], a11);                              \
        }                                                                     \
        float2 s0 = fadd2(a00, a01);                                          \
        float2 s1 = fadd2(a10, a11);                                          \
        float gt0 = s0.x + s0.y;                                              \
        float gt1 = s1.x + s1.y;                                              \
        /* activations: prescale folded into weights -> MUFU.TANH directly */ \
        float a0 = fmaf(A0, tanh_approx(gt0), B0);                            \
        float a1 = fmaf(0.5f, tanh_approx(gt1), 0.5f);                        \
        float p0 = __shfl_xor_sync(mask, a0, 1);                              \
        float p1 = __shfl_xor_sync(mask, a1, 1);                              \
        float ai = odd ? p0 : a0;                                             \
        float af = odd ? p1 : a1;                                             \
        float ag = odd ? a0 : p0;                                             \
        float ao = odd ? a1 : p1;                                             \
        c = fmaf(af, c, ai * ag);                                             \
        float hn = ao * tanh_approx(c);                                       \
        if (!odd) {                                                           \
            (WROW)[u] = hn;                                                   \
            g_hs[(t + (S)) * HH + u] = hn;                                    \
        }                                                                     \
        __syncthreads();                                                      \
    }

    #pragma unroll 1
    for (int t = 0; t < TT; t += 2, xr += 6) {
        BODY(0, hp0, &sh[1][0])
        BODY(1, hp1, &sh[0][0])
    }
#undef BODY
}

// ---------------------------------------------------------------------------
// Projection (separate full-grid kernel): out[t] = sigmoid(hs[t,:].Wl + b).
// One warp per timestep; lanes 0..24 each take one float4 of the row.
// ---------------------------------------------------------------------------
__global__ void k_proj(const float* __restrict__ Wlin,
                       const float* __restrict__ blin,
                       float* __restrict__ out) {
    int gw = (blockIdx.x * blockDim.x + threadIdx.x) >> 5;
    int l  = threadIdx.x & 31;
    if (gw >= TT) return;
    float s = 0.0f;
    if (l < 25) {
        float4 hv = reinterpret_cast<const float4*>(g_hs + gw * HH)[l];
        float4 wv = reinterpret_cast<const float4*>(Wlin)[l];
        s = hv.x * wv.x + hv.y * wv.y + hv.z * wv.z + hv.w * wv.w;
    }
    #pragma unroll
    for (int off = 16; off; off >>= 1)
        s += __shfl_xor_sync(0xffffffffu, s, off);
    if (l == 0) {
        float z = s + blin[0];
        out[gw] = rcp_approx(1.0f + ex2_approx(-LOG2E * z));
    }
}

// ---------------------------------------------------------------------------
// Launch.  Inputs: input_x, W_ih, W_hh, b_ih, b_hh, W_lin, b_lin
// ---------------------------------------------------------------------------
extern "C" void kernel_launch(void* const* d_in, const int* in_sizes, int n_in,
                              void* d_out, int out_size) {
    const float* x    = (const float*)d_in[0];
    const float* Wih  = (const float*)d_in[1];
    const float* Whh  = (const float*)d_in[2];
    const float* bih  = (const float*)d_in[3];
    const float* bhh  = (const float*)d_in[4];
    const float* Wlin = (const float*)d_in[5];
    const float* blin = (const float*)d_in[6];
    float* out = (float*)d_out;

    (void)in_sizes; (void)n_in; (void)out_size;

    const int smem_bytes = TT * 3 * (int)sizeof(float);   // 192 KB (x only)
    static bool attr_set = false;
    if (!attr_set) {
        cudaFuncSetAttribute(k_lstm_seq,
                             cudaFuncAttributeMaxDynamicSharedMemorySize,
                             smem_bytes);
        attr_set = true;
    }

    k_lstm_seq<<<1, 200, smem_bytes>>>(x, Whh, Wih, bih, bhh);
    {
        int threads = 256;   // 8 warps -> 8 timesteps per block
        int blocks = (TT * 32 + threads - 1) / threads;
        k_proj<<<blocks, threads>>>(Wlin, blin, out);
    }
}